// round 3
// baseline (speedup 1.0000x reference)
#include <cuda_runtime.h>
#include <cstring>

#define FNUM 32
#define BNUM 2048
#define KNUM 64
#define HNUM 64
#define NPAIR 496
#define NCHUNK 8
#define PAIRS_PER_CHUNK 62   // 496 / 8

// Scratch (no allocations allowed): gathered+transposed embeddings and partial logits.
__device__ float g_V[FNUM * KNUM * BNUM];          // [f][k][b], 16.8 MB (L2-resident)
__device__ float g_partial[NCHUNK * BNUM];         // per-pair-chunk partial logits

// ---- packed f32x2 helpers (FFMA2: 2 fp32 MACs per instruction on sm_103a) ----
__device__ __forceinline__ float2 ffma2(float2 a, float2 b, float2 c) {
    unsigned long long aa, bb, cc;
    memcpy(&aa, &a, 8); memcpy(&bb, &b, 8); memcpy(&cc, &c, 8);
    asm("fma.rn.f32x2 %0, %1, %2, %0;" : "+l"(cc) : "l"(aa), "l"(bb));
    float2 r; memcpy(&r, &cc, 8);
    return r;
}
__device__ __forceinline__ float2 fmul2(float2 a, float2 b) {
    unsigned long long aa, bb, dd;
    memcpy(&aa, &a, 8); memcpy(&bb, &b, 8);
    asm("mul.rn.f32x2 %0, %1, %2;" : "=l"(dd) : "l"(aa), "l"(bb));
    float2 r; memcpy(&r, &dd, 8);
    return r;
}

// ---------------- kernel 0: embedding gather + transpose to [f][k][b] ----------------
__global__ void __launch_bounds__(256) afm_gather(const int* __restrict__ x,
                                                  const float* __restrict__ emb_v) {
    int t = blockIdx.x * 256 + threadIdx.x;        // t = f*B + b, < F*B
    int f = t >> 11;                               // /2048
    int b = t & 2047;
    long long idx = x[t];
    const float4* src = reinterpret_cast<const float4*>(emb_v + idx * KNUM);
    float* dst = g_V + (size_t)f * KNUM * BNUM + b;
#pragma unroll
    for (int q = 0; q < 16; q++) {
        float4 v = __ldg(src + q);
        dst[(q * 4 + 0) * BNUM] = v.x;
        dst[(q * 4 + 1) * BNUM] = v.y;
        dst[(q * 4 + 2) * BNUM] = v.z;
        dst[(q * 4 + 3) * BNUM] = v.w;
    }
}

// ---------------- kernel 1: main pair-MLP compute ----------------
// grid = (B/32 btiles, NCHUNK pair-chunks), 256 threads (8 warps).
// Each warp: one pair at a time, 32 batch elements.
// Lane (hgrp = lid>>2 in 0..7, bgrp = lid&3 in 0..3) owns an 8h x 8b register tile.
__global__ void __launch_bounds__(256, 2) afm_main(const float* __restrict__ at_w,
                                                   const float* __restrict__ at_b,
                                                   const float* __restrict__ at_h,
                                                   const float* __restrict__ pvec) {
    // at_w padded: row stride 68, +4 word skew for h>=32 => all 32 banks distinct
    __shared__ float w_s[KNUM * 68];
    __shared__ float ab_s[HNUM];
    __shared__ float ah_s[HNUM];
    __shared__ float p_s[KNUM];
    __shared__ float sPart[8][32];

    int tid = threadIdx.x;
    for (int i = tid; i < KNUM * HNUM; i += 256) {
        int k = i >> 6, h = i & 63;
        w_s[k * 68 + h + ((h >> 5) << 2)] = at_w[i];
    }
    if (tid < 64) {
        ab_s[tid] = at_b[tid];
        ah_s[tid] = at_h[tid];
        p_s[tid]  = pvec[tid];
    }
    __syncthreads();

    int warp = tid >> 5, lid = tid & 31;
    int bgrp = lid & 3, hgrp = lid >> 2;
    int b0 = blockIdx.x * 32;
    int chunk = blockIdx.y;
    int bcol = b0 + bgrp * 8;
    int hoff = hgrp * 8 + ((hgrp >= 4) ? 4 : 0);

    float cacc[8];
#pragma unroll
    for (int t = 0; t < 8; t++) cacc[t] = 0.f;

    for (int pp = chunk * PAIRS_PER_CHUNK + warp; pp < (chunk + 1) * PAIRS_PER_CHUNK; pp += 8) {
        // decode pair index -> (fi, fj), warp-uniform
        int rem = pp, fi = 0;
        while (rem >= (FNUM - 1) - fi) { rem -= (FNUM - 1) - fi; fi++; }
        int fj = fi + 1 + rem;
        const float* vi = g_V + (size_t)fi * KNUM * BNUM + bcol;
        const float* vj = g_V + (size_t)fj * KNUM * BNUM + bcol;

        float2 acc[8][4];
        float2 pd[4];
#pragma unroll
        for (int hh = 0; hh < 8; hh++)
#pragma unroll
            for (int m = 0; m < 4; m++) acc[hh][m] = make_float2(0.f, 0.f);
#pragma unroll
        for (int m = 0; m < 4; m++) pd[m] = make_float2(0.f, 0.f);

#pragma unroll 2
        for (int k = 0; k < KNUM; k++) {
            const float4 a0 = *reinterpret_cast<const float4*>(vi + k * BNUM);
            const float4 a1 = *reinterpret_cast<const float4*>(vi + k * BNUM + 4);
            const float4 c0 = *reinterpret_cast<const float4*>(vj + k * BNUM);
            const float4 c1 = *reinterpret_cast<const float4*>(vj + k * BNUM + 4);
            float2 vv[4];
            vv[0] = fmul2(make_float2(a0.x, a0.y), make_float2(c0.x, c0.y));
            vv[1] = fmul2(make_float2(a0.z, a0.w), make_float2(c0.z, c0.w));
            vv[2] = fmul2(make_float2(a1.x, a1.y), make_float2(c1.x, c1.y));
            vv[3] = fmul2(make_float2(a1.z, a1.w), make_float2(c1.z, c1.w));

            float pk = p_s[k];
            float2 pk2 = make_float2(pk, pk);
#pragma unroll
            for (int m = 0; m < 4; m++) pd[m] = ffma2(vv[m], pk2, pd[m]);

            const float* wr = &w_s[k * 68 + hoff];
            float4 wa = *reinterpret_cast<const float4*>(wr);
            float4 wb = *reinterpret_cast<const float4*>(wr + 4);
            float wreg[8] = {wa.x, wa.y, wa.z, wa.w, wb.x, wb.y, wb.z, wb.w};
#pragma unroll
            for (int hh = 0; hh < 8; hh++) {
                float2 w2 = make_float2(wreg[hh], wreg[hh]);
#pragma unroll
                for (int m = 0; m < 4; m++) acc[hh][m] = ffma2(vv[m], w2, acc[hh][m]);
            }
        }

        // epilogue: relu + bias, dot with at_h over this lane's 8 h values
        float s[8];
#pragma unroll
        for (int t = 0; t < 8; t++) s[t] = 0.f;
#pragma unroll
        for (int hh = 0; hh < 8; hh++) {
            int h = hgrp * 8 + hh;
            float bia = ab_s[h];
            float ahv = ah_s[h];
#pragma unroll
            for (int m = 0; m < 4; m++) {
                float t0 = fmaxf(acc[hh][m].x + bia, 0.f);
                float t1 = fmaxf(acc[hh][m].y + bia, 0.f);
                s[2 * m]     = fmaf(t0, ahv, s[2 * m]);
                s[2 * m + 1] = fmaf(t1, ahv, s[2 * m + 1]);
            }
        }
        // reduce scores across the 8 h-groups (lanes differing in bits 2..4)
#pragma unroll
        for (int t = 0; t < 8; t++) {
            s[t] += __shfl_xor_sync(0xffffffffu, s[t], 4);
            s[t] += __shfl_xor_sync(0xffffffffu, s[t], 8);
            s[t] += __shfl_xor_sync(0xffffffffu, s[t], 16);
        }
        float pdf[8] = {pd[0].x, pd[0].y, pd[1].x, pd[1].y,
                        pd[2].x, pd[2].y, pd[3].x, pd[3].y};
#pragma unroll
        for (int t = 0; t < 8; t++) cacc[t] = fmaf(s[t], pdf[t], cacc[t]);
    }

    if (hgrp == 0) {
#pragma unroll
        for (int t = 0; t < 8; t++) sPart[warp][bgrp * 8 + t] = cacc[t];
    }
    __syncthreads();
    if (tid < 32) {
        float sum = 0.f;
#pragma unroll
        for (int w = 0; w < 8; w++) sum += sPart[w][tid];
        g_partial[chunk * BNUM + b0 + tid] = sum;
    }
}

// ---------------- kernel 2: first-order FM + reduce partials + sigmoid ----------------
__global__ void __launch_bounds__(256) afm_finish(const int* __restrict__ x,
                                                  const float* __restrict__ w0,
                                                  const float* __restrict__ w1,
                                                  float* __restrict__ out) {
    int b = blockIdx.x * 256 + threadIdx.x;
    if (b >= BNUM) return;
    float fm1 = w0[0];
#pragma unroll
    for (int f = 0; f < FNUM; f++) fm1 += __ldg(&w1[x[f * BNUM + b]]);
    float logit = fm1;
#pragma unroll
    for (int c = 0; c < NCHUNK; c++) logit += g_partial[c * BNUM + b];
    out[b] = 1.f / (1.f + expf(-logit));
}

extern "C" void kernel_launch(void* const* d_in, const int* in_sizes, int n_in,
                              void* d_out, int out_size) {
    const int*   x     = (const int*)d_in[0];
    const float* emb_v = (const float*)d_in[1];
    const float* at_w  = (const float*)d_in[2];
    const float* at_b  = (const float*)d_in[3];
    const float* at_h  = (const float*)d_in[4];
    const float* p     = (const float*)d_in[5];
    const float* w0    = (const float*)d_in[6];
    const float* w1    = (const float*)d_in[7];
    float* out = (float*)d_out;

    afm_gather<<<(FNUM * BNUM) / 256, 256>>>(x, emb_v);
    dim3 g1(BNUM / 32, NCHUNK);
    afm_main<<<g1, 256>>>(at_w, at_b, at_h, p);
    afm_finish<<<(BNUM + 255) / 256, 256>>>(x, w0, w1, out);
}

// round 7
// speedup vs baseline: 4.9145x; 4.9145x over previous
#include <cuda_runtime.h>
#include <cuda_bf16.h>
#include <cstdint>

#define FNUM 32
#define BNUM 2048
#define KNUM 64
#define HNUM 64
#define NBLK 36          // 8*9/2 field-group blocks (groups of 4 fields)
#define BT   128         // batch tile
#define NBT  (BNUM/BT)   // 16

// ---------------- device scratch (no allocations allowed) ----------------
__device__ __nv_bfloat16 g_Vb[(size_t)FNUM * BNUM * KNUM];  // [f][b][k], 8.4 MB
__device__ float g_partial[NBLK * BNUM];

// ---------------- dynamic shared-memory layout (bytes) ----------------
#define SO_AB   0           // 64 f32
#define SO_AH   256         // 64 f32
#define SO_W    1024        // at_w^T [64h x 64k] bf16, XOR-chunk swizzle (8 KB)
#define SO_P    9216        // p tile [8n x 64k] bf16 (row0 = p, rest 0)   (1 KB)
#define SO_I    10240       // 4 cached field tiles, 16 KB each            (64 KB)
#define SO_J    75776       // streamed field tile                         (16 KB)
#define SMEM_TOTAL 92160

static __device__ __forceinline__ uint32_t smem_u32(const void* p) {
    uint32_t a;
    asm("{ .reg .u64 t; cvta.to.shared.u64 t, %1; cvt.u32.u64 %0, t; }" : "=r"(a) : "l"(p));
    return a;
}
static __device__ __forceinline__ uint32_t bmul2(uint32_t a, uint32_t b) {
    uint32_t r;
    asm("mul.bf16x2 %0, %1, %2;" : "=r"(r) : "r"(a), "r"(b));
    return r;
}
static __device__ __forceinline__ void ldsm_x4(uint32_t& r0, uint32_t& r1,
                                               uint32_t& r2, uint32_t& r3, uint32_t addr) {
    asm volatile("ldmatrix.sync.aligned.m8n8.x4.shared.b16 {%0,%1,%2,%3}, [%4];"
                 : "=r"(r0), "=r"(r1), "=r"(r2), "=r"(r3) : "r"(addr));
}
static __device__ __forceinline__ void ldsm_x2(uint32_t& r0, uint32_t& r1, uint32_t addr) {
    asm volatile("ldmatrix.sync.aligned.m8n8.x2.shared.b16 {%0,%1}, [%2];"
                 : "=r"(r0), "=r"(r1) : "r"(addr));
}
static __device__ __forceinline__ void mma16816(float* d, const uint32_t* a, const uint32_t* b) {
    asm volatile(
        "mma.sync.aligned.m16n8k16.row.col.f32.bf16.bf16.f32 "
        "{%0,%1,%2,%3}, {%4,%5,%6,%7}, {%8,%9}, {%0,%1,%2,%3};"
        : "+f"(d[0]), "+f"(d[1]), "+f"(d[2]), "+f"(d[3])
        : "r"(a[0]), "r"(a[1]), "r"(a[2]), "r"(a[3]), "r"(b[0]), "r"(b[1]));
}

// Load one 128x64 bf16 field tile (16 KB, gmem-contiguous) into SMEM with
// per-row XOR chunk rotation (chunk' = chunk ^ (row&7)) -> conflict-free ldmatrix.
static __device__ __forceinline__ void load_tile(char* dst, const __nv_bfloat16* src, int tid) {
    const uint4* s = (const uint4*)src;
#pragma unroll
    for (int it = 0; it < 4; it++) {
        int u = tid + it * 256;                 // uint4 index, < 1024
        int row = u >> 3, c = u & 7;
        *(uint4*)(dst + row * 128 + ((c ^ (row & 7)) << 4)) = s[u];
    }
}

// ---------------- kernel 0: gather + fp32->bf16 ----------------
__global__ void __launch_bounds__(256) afm_gather(const int* __restrict__ x,
                                                  const float* __restrict__ emb) {
    int t = blockIdx.x * 256 + threadIdx.x;     // t = f*B + b  (row index of g_Vb)
    const float4* src = (const float4*)(emb + (size_t)x[t] * KNUM);
    uint4* dst = (uint4*)(g_Vb + (size_t)t * KNUM);
#pragma unroll
    for (int q = 0; q < 8; q++) {
        float4 a = __ldg(src + 2 * q);
        float4 b = __ldg(src + 2 * q + 1);
        __nv_bfloat162 c0 = __floats2bfloat162_rn(a.x, a.y);
        __nv_bfloat162 c1 = __floats2bfloat162_rn(a.z, a.w);
        __nv_bfloat162 c2 = __floats2bfloat162_rn(b.x, b.y);
        __nv_bfloat162 c3 = __floats2bfloat162_rn(b.z, b.w);
        uint4 o;
        o.x = *(uint32_t*)&c0; o.y = *(uint32_t*)&c1;
        o.z = *(uint32_t*)&c2; o.w = *(uint32_t*)&c3;
        dst[q] = o;
    }
}

// ---------------- kernel 1: warp-MMA pair MLP ----------------
// grid = (NBT, NBLK), 256 threads. Warp w owns batch rows [w*16, w*16+16).
// Per pair: A = VV fragments built in registers (ldmatrix Vi, Vj + mul.bf16x2),
// B = [at_w^T | p] (N=72) held in registers; 36 mma.sync per pair per warp.
__global__ void __launch_bounds__(256) afm_tc(const float* __restrict__ at_w,
                                              const float* __restrict__ at_b,
                                              const float* __restrict__ at_h,
                                              const float* __restrict__ pvec)
{
    extern __shared__ __align__(1024) char sm[];
    uint32_t smb = smem_u32(sm);
    int tid = threadIdx.x, warp = tid >> 5, lane = tid & 31;

    // field-block decode: blockIdx.y -> (bi <= bj) over 8 groups of 4 fields
    int t = blockIdx.y, bi = 0;
    while (t >= 8 - bi) { t -= 8 - bi; bi++; }
    int bj = bi + t;
    int b0 = blockIdx.x * BT;

    float* ab = (float*)(sm + SO_AB);
    float* ah = (float*)(sm + SO_AH);
    if (tid < 64) { ab[tid] = at_b[tid]; ah[tid] = at_h[tid]; }

    // W^T tile [h rows x k cols] bf16, chunk-XOR swizzle
    for (int i = tid; i < KNUM * HNUM; i += 256) {
        int k = i >> 6, h = i & 63;             // at_w[k][h]
        int phys = (k >> 3) ^ (h & 7);
        *(__nv_bfloat16*)(sm + SO_W + h * 128 + phys * 16 + (k & 7) * 2) =
            __float2bfloat16(at_w[i]);
    }
    // p tile: zero 8x64, then row 0 = p (row 0 swizzle is identity)
    if (tid < 64) ((uint4*)(sm + SO_P))[tid] = make_uint4(0, 0, 0, 0);
    __syncthreads();
    if (tid < 64)
        *(__nv_bfloat16*)(sm + SO_P + tid * 2) = __float2bfloat16(pvec[tid]);

    // cache the 4 "I" field tiles
#pragma unroll
    for (int f = 0; f < 4; f++)
        load_tile(sm + SO_I + f * 16384,
                  g_Vb + (size_t)((bi * 4 + f) * BNUM + b0) * KNUM, tid);
    __syncthreads();

    // ---- load B fragments (held in registers, reused for all 16 pairs) ----
    // Bf[s][j]: kstep s (k16), n-tile j (j<8: h columns j*8..; j==8: p column tile)
    uint32_t Bf[4][9][2];
    {
        int r7 = lane & 7, csel = (lane >> 3) & 1;
#pragma unroll
        for (int s = 0; s < 4; s++) {
            int chunk = (2 * s + csel) ^ r7;
#pragma unroll
            for (int j = 0; j < 8; j++) {
                uint32_t addr = smb + SO_W + (j * 8 + r7) * 128 + (chunk << 4);
                ldsm_x2(Bf[s][j][0], Bf[s][j][1], addr);
            }
            uint32_t addr = smb + SO_P + r7 * 128 + (chunk << 4);
            ldsm_x2(Bf[s][8][0], Bf[s][8][1], addr);
        }
    }

    // A-fragment lane addressing (within a 128x64 tile):
    // row = warp*16 + (lane&15); chunk(s) = (2s + (lane>>4)) ^ (lane&7)
    uint32_t aRowOff = (uint32_t)(warp * 16 + (lane & 15)) * 128;
    uint32_t chOff[4];
#pragma unroll
    for (int s = 0; s < 4; s++)
        chOff[s] = (uint32_t)(((2 * s + (lane >> 4)) ^ (lane & 7)) << 4);

    float accLo = 0.f, accHi = 0.f;

    // per-pair lambda
    auto do_pair = [&](int viOff, int vjOff) {
        float d[9][4];
#pragma unroll
        for (int j = 0; j < 9; j++)
#pragma unroll
            for (int q = 0; q < 4; q++) d[j][q] = 0.f;

        uint32_t aBaseI = smb + viOff + aRowOff;
        uint32_t aBaseJ = smb + vjOff + aRowOff;
#pragma unroll
        for (int s = 0; s < 4; s++) {
            uint32_t vi[4], vj[4], vv[4];
            ldsm_x4(vi[0], vi[1], vi[2], vi[3], aBaseI + chOff[s]);
            ldsm_x4(vj[0], vj[1], vj[2], vj[3], aBaseJ + chOff[s]);
#pragma unroll
            for (int q = 0; q < 4; q++) vv[q] = bmul2(vi[q], vj[q]);
#pragma unroll
            for (int j = 0; j < 9; j++) mma16816(d[j], vv, Bf[s][j]);
        }

        // epilogue: score = sum_h ah*relu(d+ab); pd from n-tile 8 col 0
        float sLo = 0.f, sHi = 0.f;
        int c0 = (lane & 3) * 2;
#pragma unroll
        for (int j = 0; j < 8; j++) {
            float2 abv = *(const float2*)(ab + j * 8 + c0);
            float2 ahv = *(const float2*)(ah + j * 8 + c0);
            sLo = fmaf(fmaxf(d[j][0] + abv.x, 0.f), ahv.x, sLo);
            sLo = fmaf(fmaxf(d[j][1] + abv.y, 0.f), ahv.y, sLo);
            sHi = fmaf(fmaxf(d[j][2] + abv.x, 0.f), ahv.x, sHi);
            sHi = fmaf(fmaxf(d[j][3] + abv.y, 0.f), ahv.y, sHi);
        }
        sLo += __shfl_xor_sync(0xffffffffu, sLo, 1);
        sLo += __shfl_xor_sync(0xffffffffu, sLo, 2);
        sHi += __shfl_xor_sync(0xffffffffu, sHi, 1);
        sHi += __shfl_xor_sync(0xffffffffu, sHi, 2);
        // pd valid in lanes with (lane&3)==0 (col 0 of the p n-tile)
        accLo = fmaf(sLo, d[8][0], accLo);
        accHi = fmaf(sHi, d[8][2], accHi);
    };

    if (bi != bj) {
        for (int jj = 0; jj < 4; jj++) {
            __syncthreads();                    // J tile reusable
            load_tile(sm + SO_J, g_Vb + (size_t)((bj * 4 + jj) * BNUM + b0) * KNUM, tid);
            __syncthreads();
#pragma unroll
            for (int ii = 0; ii < 4; ii++)
                do_pair(SO_I + ii * 16384, SO_J);
        }
    } else {
#pragma unroll
        for (int jj = 1; jj < 4; jj++)
#pragma unroll
            for (int ii = 0; ii < jj; ii++)
                do_pair(SO_I + ii * 16384, SO_I + jj * 16384);
    }

    if ((lane & 3) == 0) {
        int row = warp * 16 + (lane >> 2);
        g_partial[blockIdx.y * BNUM + b0 + row]     = accLo;
        g_partial[blockIdx.y * BNUM + b0 + row + 8] = accHi;
    }
}

// ---------------- kernel 2: first-order FM + reduce + sigmoid ----------------
__global__ void __launch_bounds__(256) afm_finish(const int* __restrict__ x,
                                                  const float* __restrict__ w0,
                                                  const float* __restrict__ w1,
                                                  float* __restrict__ out) {
    int b = blockIdx.x * 256 + threadIdx.x;
    if (b >= BNUM) return;
    float fm1 = w0[0];
#pragma unroll
    for (int f = 0; f < FNUM; f++) fm1 += __ldg(&w1[x[f * BNUM + b]]);
    float logit = fm1;
#pragma unroll
    for (int c = 0; c < NBLK; c++) logit += g_partial[c * BNUM + b];
    out[b] = 1.f / (1.f + expf(-logit));
}

extern "C" void kernel_launch(void* const* d_in, const int* in_sizes, int n_in,
                              void* d_out, int out_size) {
    const int*   x     = (const int*)d_in[0];
    const float* emb_v = (const float*)d_in[1];
    const float* at_w  = (const float*)d_in[2];
    const float* at_b  = (const float*)d_in[3];
    const float* at_h  = (const float*)d_in[4];
    const float* p     = (const float*)d_in[5];
    const float* w0    = (const float*)d_in[6];
    const float* w1    = (const float*)d_in[7];
    float* out = (float*)d_out;

    cudaFuncSetAttribute(afm_tc, cudaFuncAttributeMaxDynamicSharedMemorySize, SMEM_TOTAL);

    afm_gather<<<(FNUM * BNUM) / 256, 256>>>(x, emb_v);
    dim3 g1(NBT, NBLK);
    afm_tc<<<g1, 256, SMEM_TOTAL>>>(at_w, at_b, at_h, p);
    afm_finish<<<(BNUM + 255) / 256, 256>>>(x, w0, w1, out);
}

// round 12
// speedup vs baseline: 5.2535x; 1.0690x over previous
#include <cuda_runtime.h>
#include <cuda_bf16.h>
#include <cstdint>

#define FNUM 32
#define BNUM 2048
#define KNUM 64
#define HNUM 64
#define NBLK 36          // 8*9/2 field-group blocks (groups of 4 fields)
#define BT   128         // batch tile
#define NBT  (BNUM/BT)   // 16

// ---------------- device scratch (no allocations allowed) ----------------
__device__ __nv_bfloat16 g_Vb[(size_t)FNUM * BNUM * KNUM];  // [f][b][k], 8.4 MB
__device__ float g_partial[NBLK * BNUM];

// ---------------- dynamic shared-memory layout (bytes) ----------------
#define SO_AB   0           // 64 f32
#define SO_AH   256         // 64 f32
#define SO_W    1024        // at_w^T [64h x 64k] bf16, XOR-chunk swizzle (8 KB)
#define SO_P    9216        // p tile [8n x 64k] bf16 (row0 = p, rest 0)   (1 KB)
#define SO_T    10240       // 8 field tiles, 16 KB each                   (128 KB)
#define SMEM_TOTAL (SO_T + 8 * 16384)   // 141312

static __device__ __forceinline__ uint32_t smem_u32(const void* p) {
    uint32_t a;
    asm("{ .reg .u64 t; cvta.to.shared.u64 t, %1; cvt.u32.u64 %0, t; }" : "=r"(a) : "l"(p));
    return a;
}
static __device__ __forceinline__ uint32_t bmul2(uint32_t a, uint32_t b) {
    uint32_t r;
    asm("mul.bf16x2 %0, %1, %2;" : "=r"(r) : "r"(a), "r"(b));
    return r;
}
static __device__ __forceinline__ void ldsm_x4(uint32_t& r0, uint32_t& r1,
                                               uint32_t& r2, uint32_t& r3, uint32_t addr) {
    asm volatile("ldmatrix.sync.aligned.m8n8.x4.shared.b16 {%0,%1,%2,%3}, [%4];"
                 : "=r"(r0), "=r"(r1), "=r"(r2), "=r"(r3) : "r"(addr));
}
static __device__ __forceinline__ void ldsm_x2(uint32_t& r0, uint32_t& r1, uint32_t addr) {
    asm volatile("ldmatrix.sync.aligned.m8n8.x2.shared.b16 {%0,%1}, [%2];"
                 : "=r"(r0), "=r"(r1) : "r"(addr));
}
static __device__ __forceinline__ void mma16816(float* d, const uint32_t* a, const uint32_t* b) {
    asm volatile(
        "mma.sync.aligned.m16n8k16.row.col.f32.bf16.bf16.f32 "
        "{%0,%1,%2,%3}, {%4,%5,%6,%7}, {%8,%9}, {%0,%1,%2,%3};"
        : "+f"(d[0]), "+f"(d[1]), "+f"(d[2]), "+f"(d[3])
        : "r"(a[0]), "r"(a[1]), "r"(a[2]), "r"(a[3]), "r"(b[0]), "r"(b[1]));
}

// Load one 128x64 bf16 field tile (16 KB, gmem-contiguous) into SMEM with
// per-row XOR chunk rotation (chunk' = chunk ^ (row&7)) -> conflict-free ldmatrix.
static __device__ __forceinline__ void load_tile(char* dst, const __nv_bfloat16* src, int tid) {
    const uint4* s = (const uint4*)src;
#pragma unroll
    for (int it = 0; it < 4; it++) {
        int u = tid + it * 256;                 // uint4 index, < 1024
        int row = u >> 3, c = u & 7;
        *(uint4*)(dst + row * 128 + ((c ^ (row & 7)) << 4)) = s[u];
    }
}

// ---------------- kernel 0: gather + fp32->bf16 (8 threads per row) ----------------
__global__ void __launch_bounds__(256) afm_gather(const int* __restrict__ x,
                                                  const float* __restrict__ emb) {
    int t = blockIdx.x * 256 + threadIdx.x;     // < F*B*8
    int row = t >> 3, q = t & 7;
    const float4* src = (const float4*)(emb + (size_t)__ldg(&x[row]) * KNUM) + 2 * q;
    float4 a = __ldg(src);
    float4 b = __ldg(src + 1);
    __nv_bfloat162 c0 = __floats2bfloat162_rn(a.x, a.y);
    __nv_bfloat162 c1 = __floats2bfloat162_rn(a.z, a.w);
    __nv_bfloat162 c2 = __floats2bfloat162_rn(b.x, b.y);
    __nv_bfloat162 c3 = __floats2bfloat162_rn(b.z, b.w);
    uint4 o;
    o.x = *(uint32_t*)&c0; o.y = *(uint32_t*)&c1;
    o.z = *(uint32_t*)&c2; o.w = *(uint32_t*)&c3;
    ((uint4*)(g_Vb + (size_t)row * KNUM))[q] = o;
}

// ---------------- kernel 1: warp-MMA pair MLP ----------------
// grid = (NBT, NBLK), 256 threads. Warp w owns batch rows [w*16, w*16+16).
// All 8 field tiles of the block cached in SMEM up front (single barrier);
// held-side (Vj) fragments hoisted into registers per j-group.
__global__ void __launch_bounds__(256) afm_tc(const float* __restrict__ at_w,
                                              const float* __restrict__ at_b,
                                              const float* __restrict__ at_h,
                                              const float* __restrict__ pvec)
{
    extern __shared__ __align__(1024) char sm[];
    uint32_t smb = smem_u32(sm);
    int tid = threadIdx.x, warp = tid >> 5, lane = tid & 31;

    // field-block decode: blockIdx.y -> (bi <= bj) over 8 groups of 4 fields
    int t = blockIdx.y, bi = 0;
    while (t >= 8 - bi) { t -= 8 - bi; bi++; }
    int bj = bi + t;
    int b0 = blockIdx.x * BT;
    bool diag = (bi == bj);

    float* ab = (float*)(sm + SO_AB);
    float* ah = (float*)(sm + SO_AH);
    if (tid < 64) { ab[tid] = at_b[tid]; ah[tid] = at_h[tid]; }

    // W^T tile [h rows x k cols] bf16, chunk-XOR swizzle
    for (int i = tid; i < KNUM * HNUM; i += 256) {
        int k = i >> 6, h = i & 63;             // at_w[k][h]
        int phys = (k >> 3) ^ (h & 7);
        *(__nv_bfloat16*)(sm + SO_W + h * 128 + phys * 16 + (k & 7) * 2) =
            __float2bfloat16(at_w[i]);
    }
    // p tile: row 0 = p (tid<64, row-0 swizzle is identity), rows 1-7 zero (tids 64..119)
    if (tid < 64)
        *(__nv_bfloat16*)(sm + SO_P + tid * 2) = __float2bfloat16(pvec[tid]);
    else if (tid < 120)
        ((uint4*)(sm + SO_P + 128))[tid - 64] = make_uint4(0, 0, 0, 0);

    // cache field tiles: I group -> slots 0..3; J group (off-diag) -> slots 4..7
#pragma unroll
    for (int f = 0; f < 4; f++)
        load_tile(sm + SO_T + f * 16384,
                  g_Vb + (size_t)((bi * 4 + f) * BNUM + b0) * KNUM, tid);
    if (!diag) {
#pragma unroll
        for (int f = 0; f < 4; f++)
            load_tile(sm + SO_T + (4 + f) * 16384,
                      g_Vb + (size_t)((bj * 4 + f) * BNUM + b0) * KNUM, tid);
    }
    __syncthreads();    // the only barrier in the kernel body

    // ---- load B fragments (held in registers, reused for all pairs) ----
    // Bf[s][j]: kstep s (k16), n-tile j (j<8: h columns j*8..; j==8: p column tile)
    uint32_t Bf[4][9][2];
    {
        int r7 = lane & 7, csel = (lane >> 3) & 1;
#pragma unroll
        for (int s = 0; s < 4; s++) {
            int chunk = (2 * s + csel) ^ r7;
#pragma unroll
            for (int j = 0; j < 8; j++) {
                uint32_t addr = smb + SO_W + (j * 8 + r7) * 128 + (chunk << 4);
                ldsm_x2(Bf[s][j][0], Bf[s][j][1], addr);
            }
            uint32_t addr = smb + SO_P + r7 * 128 + (chunk << 4);
            ldsm_x2(Bf[s][8][0], Bf[s][8][1], addr);
        }
    }

    // A-fragment lane addressing (within a 128x64 tile):
    // row = warp*16 + (lane&15); chunk(s) = (2s + (lane>>4)) ^ (lane&7)
    uint32_t aRowOff = (uint32_t)(warp * 16 + (lane & 15)) * 128;
    uint32_t chOff[4];
#pragma unroll
    for (int s = 0; s < 4; s++)
        chOff[s] = (uint32_t)(((2 * s + (lane >> 4)) ^ (lane & 7)) << 4);

    float accLo = 0.f, accHi = 0.f;

    // stream-side pair body against held Vj fragments
    auto do_pair_held = [&](int viOff, const uint32_t (&vjF)[4][4]) {
        float d[9][4];
#pragma unroll
        for (int j = 0; j < 9; j++)
#pragma unroll
            for (int q = 0; q < 4; q++) d[j][q] = 0.f;

        uint32_t aBaseI = smb + viOff + aRowOff;
#pragma unroll
        for (int s = 0; s < 4; s++) {
            uint32_t vi[4], vv[4];
            ldsm_x4(vi[0], vi[1], vi[2], vi[3], aBaseI + chOff[s]);
#pragma unroll
            for (int q = 0; q < 4; q++) vv[q] = bmul2(vi[q], vjF[s][q]);
#pragma unroll
            for (int j = 0; j < 9; j++) mma16816(d[j], vv, Bf[s][j]);
        }

        // epilogue: score = sum_h ah*relu(d+ab); pd from n-tile 8 col 0
        float sLo = 0.f, sHi = 0.f;
        int c0 = (lane & 3) * 2;
#pragma unroll
        for (int j = 0; j < 8; j++) {
            float2 abv = *(const float2*)(ab + j * 8 + c0);
            float2 ahv = *(const float2*)(ah + j * 8 + c0);
            sLo = fmaf(fmaxf(d[j][0] + abv.x, 0.f), ahv.x, sLo);
            sLo = fmaf(fmaxf(d[j][1] + abv.y, 0.f), ahv.y, sLo);
            sHi = fmaf(fmaxf(d[j][2] + abv.x, 0.f), ahv.x, sHi);
            sHi = fmaf(fmaxf(d[j][3] + abv.y, 0.f), ahv.y, sHi);
        }
        sLo += __shfl_xor_sync(0xffffffffu, sLo, 1);
        sLo += __shfl_xor_sync(0xffffffffu, sLo, 2);
        sHi += __shfl_xor_sync(0xffffffffu, sHi, 1);
        sHi += __shfl_xor_sync(0xffffffffu, sHi, 2);
        // pd valid in lanes with (lane&3)==0 (col 0 of the p n-tile)
        accLo = fmaf(sLo, d[8][0], accLo);
        accHi = fmaf(sHi, d[8][2], accHi);
    };

    auto load_frags = [&](int off, uint32_t (&F)[4][4]) {
#pragma unroll
        for (int s = 0; s < 4; s++)
            ldsm_x4(F[s][0], F[s][1], F[s][2], F[s][3], smb + off + aRowOff + chOff[s]);
    };

    uint32_t vjF[4][4];
    if (!diag) {
#pragma unroll
        for (int jj = 0; jj < 4; jj++) {
            load_frags(SO_T + (4 + jj) * 16384, vjF);
#pragma unroll
            for (int ii = 0; ii < 4; ii++)
                do_pair_held(SO_T + ii * 16384, vjF);
        }
    } else {
#pragma unroll
        for (int jj = 1; jj < 4; jj++) {
            load_frags(SO_T + jj * 16384, vjF);
#pragma unroll
            for (int ii = 0; ii < 3; ii++)
                if (ii < jj)
                    do_pair_held(SO_T + ii * 16384, vjF);
        }
    }

    if ((lane & 3) == 0) {
        int row = warp * 16 + (lane >> 2);
        g_partial[blockIdx.y * BNUM + b0 + row]     = accLo;
        g_partial[blockIdx.y * BNUM + b0 + row + 8] = accHi;
    }
}

// ---------------- kernel 2: warp-per-b first-order FM + reduce + sigmoid ----------------
__global__ void __launch_bounds__(256) afm_finish(const int* __restrict__ x,
                                                  const float* __restrict__ w0,
                                                  const float* __restrict__ w1,
                                                  float* __restrict__ out) {
    int warp = threadIdx.x >> 5, lane = threadIdx.x & 31;
    int b = blockIdx.x * 8 + warp;              // 256 blocks * 8 warps = 2048
    float s = __ldg(&w1[__ldg(&x[lane * BNUM + b])]);   // f = lane (32 fields)
    s += g_partial[lane * BNUM + b];                    // chunk c = lane
    if (lane < NBLK - 32)
        s += g_partial[(32 + lane) * BNUM + b];         // chunks 32..35
#pragma unroll
    for (int off = 16; off > 0; off >>= 1)
        s += __shfl_xor_sync(0xffffffffu, s, off);
    if (lane == 0)
        out[b] = 1.f / (1.f + expf(-(s + w0[0])));
}

extern "C" void kernel_launch(void* const* d_in, const int* in_sizes, int n_in,
                              void* d_out, int out_size) {
    const int*   x     = (const int*)d_in[0];
    const float* emb_v = (const float*)d_in[1];
    const float* at_w  = (const float*)d_in[2];
    const float* at_b  = (const float*)d_in[3];
    const float* at_h  = (const float*)d_in[4];
    const float* p     = (const float*)d_in[5];
    const float* w0    = (const float*)d_in[6];
    const float* w1    = (const float*)d_in[7];
    float* out = (float*)d_out;

    cudaFuncSetAttribute(afm_tc, cudaFuncAttributeMaxDynamicSharedMemorySize, SMEM_TOTAL);

    afm_gather<<<(FNUM * BNUM * 8) / 256, 256>>>(x, emb_v);
    dim3 g1(NBT, NBLK);
    afm_tc<<<g1, 256, SMEM_TOTAL>>>(at_w, at_b, at_h, p);
    afm_finish<<<BNUM / 8, 256>>>(x, w0, w1, out);
}